// round 7
// baseline (speedup 1.0000x reference)
#include <cuda_runtime.h>
#include <cuda_bf16.h>
#include <cstdint>

#define B   256
#define T   1024
#define H   128
#define I   19
#define BT  (B*T)            // 262144
#define NEL (BT*H)           // 33554432

// Scratch (device globals: allocation-free per harness rules)
__device__ float g_pre[NEL];   // pre-activations (layer0, then layer1)
__device__ float g_h1[NEL];    // layer-0 hidden outputs

typedef unsigned long long u64;

__device__ __forceinline__ u64 fma2(u64 a, u64 b, u64 c) {
    u64 d;
    asm("fma.rn.f32x2 %0, %1, %2, %3;" : "=l"(d) : "l"(a), "l"(b), "l"(c));
    return d;
}
__device__ __forceinline__ u64 add2(u64 a, u64 b) {
    u64 d;
    asm("add.rn.f32x2 %0, %1, %2;" : "=l"(d) : "l"(a), "l"(b));
    return d;
}
__device__ __forceinline__ float red2(u64 a) {
    float x, y;
    asm("mov.b64 {%0, %1}, %2;" : "=f"(x), "=f"(y) : "l"(a));
    return x + y;
}
__device__ __forceinline__ float fast_tanh(float x) {
    float r;
    asm("tanh.approx.f32 %0, %1;" : "=f"(r) : "f"(x));
    return r;
}
__device__ __forceinline__ void cp16(uint32_t daddr, const void* gptr) {
    asm volatile("cp.async.ca.shared.global [%0], [%1], 16;\n"
                 :: "r"(daddr), "l"(gptr));
}

// ---------------------------------------------------------------------------
// Kernel 1: pre0 (proven in round 5)
// ---------------------------------------------------------------------------
#define P0_ROWS 64
#define P0_F4   ((P0_ROWS * I) / 4)   // 304

__global__ void __launch_bounds__(128)
pre0_kernel(const float* __restrict__ x,
            const float* __restrict__ W,
            const float* __restrict__ bi,
            const float* __restrict__ bh) {
    __shared__ __align__(16) float xs[P0_ROWS * I];
    const int j = threadIdx.x;

    float w[I];
#pragma unroll
    for (int f = 0; f < I; f++) w[f] = __ldg(W + j * I + f);
    const float bias = __ldg(bi + j) + __ldg(bh + j);

    const int rbeg = blockIdx.x * P0_ROWS;
    const float4* src = reinterpret_cast<const float4*>(x + (size_t)rbeg * I);
    float4* dst = reinterpret_cast<float4*>(xs);
    dst[j] = src[j];
    dst[j + 128] = src[j + 128];
    if (j < P0_F4 - 256) dst[j + 256] = src[j + 256];
    __syncthreads();

    float* outp = g_pre + (size_t)rbeg * H + j;
#pragma unroll 4
    for (int r = 0; r < P0_ROWS; r += 4) {
        float a0 = bias, a1 = bias, a2 = bias, a3 = bias;
#pragma unroll
        for (int f = 0; f < I; f++) {
            a0 = fmaf(xs[(r + 0) * I + f], w[f], a0);
            a1 = fmaf(xs[(r + 1) * I + f], w[f], a1);
            a2 = fmaf(xs[(r + 2) * I + f], w[f], a2);
            a3 = fmaf(xs[(r + 3) * I + f], w[f], a3);
        }
        outp[(r + 0) * H] = a0;
        outp[(r + 1) * H] = a1;
        outp[(r + 2) * H] = a2;
        outp[(r + 3) * H] = a3;
    }
}

// ---------------------------------------------------------------------------
// Kernel 2: recurrent scan, TWO batch rows per CTA.
// 128 threads; thread j owns unit j for rows r0=2*blk and r1=2*blk+1, with
// W_hh row j in 64 packed f32x2 registers REUSED for both rows. The two
// independent dot-product chains interleave into the latency holes that
// pinned the single-row step at ~850 cyc. Grid=128 -> 1 CTA/SM.
// ---------------------------------------------------------------------------
__global__ void __launch_bounds__(128, 1)
scan_kernel(int layer, const float* __restrict__ Whh, float* __restrict__ dout) {
    __shared__ __align__(16) float h0A[H], h0B[H], h1A[H], h1B[H];
    const int j = threadIdx.x;
    const float* __restrict__ pre = g_pre;
    float* __restrict__ out = (layer == 0) ? g_h1 : dout;

    u64 wp[64];
    const u64* wrow = reinterpret_cast<const u64*>(Whh + j * H);
#pragma unroll
    for (int i = 0; i < 64; i++) wp[i] = __ldg(wrow + i);

    h0A[j] = 0.0f;
    h1A[j] = 0.0f;
    const int base0 = (2 * blockIdx.x)     * (T * H) + j;
    const int base1 = (2 * blockIdx.x + 1) * (T * H) + j;

    float pA0 = __ldg(pre + base0);
    float pA1 = __ldg(pre + base1);
    float pB0 = __ldg(pre + base0 + H);
    float pB1 = __ldg(pre + base1 + H);
    __syncthreads();

#pragma unroll 1
    for (int t = 0; t < T; t += 2) {
        // ---- phase A: read h*A, write h*B ----
        {
            const ulonglong2* hp0 = reinterpret_cast<const ulonglong2*>(h0A);
            const ulonglong2* hp1 = reinterpret_cast<const ulonglong2*>(h1A);
            u64 a0=0,a1=0,a2=0,a3=0, c0=0,c1=0,c2=0,c3=0;
#pragma unroll
            for (int i = 0; i < 16; i++) {
                ulonglong2 q0 = hp0[2*i], q1 = hp0[2*i+1];
                ulonglong2 r0 = hp1[2*i], r1 = hp1[2*i+1];
                a0 = fma2(wp[4*i+0], q0.x, a0);
                c0 = fma2(wp[4*i+0], r0.x, c0);
                a1 = fma2(wp[4*i+1], q0.y, a1);
                c1 = fma2(wp[4*i+1], r0.y, c1);
                a2 = fma2(wp[4*i+2], q1.x, a2);
                c2 = fma2(wp[4*i+2], r1.x, c2);
                a3 = fma2(wp[4*i+3], q1.y, a3);
                c3 = fma2(wp[4*i+3], r1.y, c3);
            }
            float h0 = fast_tanh(pA0 + red2(add2(add2(a0,a2), add2(a1,a3))));
            float h1 = fast_tanh(pA1 + red2(add2(add2(c0,c2), add2(c1,c3))));
            h0B[j] = h0;
            h1B[j] = h1;
            out[base0 + t * H] = h0;
            out[base1 + t * H] = h1;
            int tn = (t + 2 < T) ? (t + 2) : (T - 1);
            pA0 = __ldg(pre + base0 + tn * H);
            pA1 = __ldg(pre + base1 + tn * H);
            __syncthreads();
        }
        // ---- phase B: read h*B, write h*A ----
        {
            const ulonglong2* hp0 = reinterpret_cast<const ulonglong2*>(h0B);
            const ulonglong2* hp1 = reinterpret_cast<const ulonglong2*>(h1B);
            u64 a0=0,a1=0,a2=0,a3=0, c0=0,c1=0,c2=0,c3=0;
#pragma unroll
            for (int i = 0; i < 16; i++) {
                ulonglong2 q0 = hp0[2*i], q1 = hp0[2*i+1];
                ulonglong2 r0 = hp1[2*i], r1 = hp1[2*i+1];
                a0 = fma2(wp[4*i+0], q0.x, a0);
                c0 = fma2(wp[4*i+0], r0.x, c0);
                a1 = fma2(wp[4*i+1], q0.y, a1);
                c1 = fma2(wp[4*i+1], r0.y, c1);
                a2 = fma2(wp[4*i+2], q1.x, a2);
                c2 = fma2(wp[4*i+2], r1.x, c2);
                a3 = fma2(wp[4*i+3], q1.y, a3);
                c3 = fma2(wp[4*i+3], r1.y, c3);
            }
            float h0 = fast_tanh(pB0 + red2(add2(add2(a0,a2), add2(a1,a3))));
            float h1 = fast_tanh(pB1 + red2(add2(add2(c0,c2), add2(c1,c3))));
            h0A[j] = h0;
            h1A[j] = h1;
            out[base0 + (t+1) * H] = h0;
            out[base1 + (t+1) * H] = h1;
            int tn = (t + 3 < T) ? (t + 3) : (T - 1);
            pB0 = __ldg(pre + base0 + tn * H);
            pB1 = __ldg(pre + base1 + tn * H);
            __syncthreads();
        }
    }
}

// ---------------------------------------------------------------------------
// Kernel 3: layer-1 input projection, 4-stage cp.async pipeline (round 5).
// ---------------------------------------------------------------------------
#define PROJ_BLOCKS 512
#define PROJ_ROWS   (BT / PROJ_BLOCKS)   // 512
#define PTILE       8
#define NTILES      (PROJ_ROWS / PTILE)  // 64
#define NSTAGE      4
#define STAGE_BYTES (PTILE * H * 4)      // 4096

__global__ void __launch_bounds__(128, 2)
proj_kernel(const float* __restrict__ W,
            const float* __restrict__ bi,
            const float* __restrict__ bh) {
    __shared__ __align__(16) float sh[NSTAGE][PTILE * H];
    const int j = threadIdx.x;
    const uint32_t shbase = (uint32_t)__cvta_generic_to_shared(sh);

    u64 wp[64];
    const u64* wrow = reinterpret_cast<const u64*>(W + j * H);
#pragma unroll
    for (int i = 0; i < 64; i++) wp[i] = __ldg(wrow + i);

    const float bias = __ldg(bi + j) + __ldg(bh + j);
    const int rbeg = blockIdx.x * PROJ_ROWS;

#pragma unroll
    for (int s = 0; s < 3; s++) {
        const float4* src = reinterpret_cast<const float4*>(
            g_h1 + (size_t)(rbeg + s * PTILE) * H);
        uint32_t d = shbase + s * STAGE_BYTES + j * 16;
        cp16(d, src + j);
        cp16(d + 2048, src + j + 128);
        asm volatile("cp.async.commit_group;\n");
    }

#pragma unroll 1
    for (int ti = 0; ti < NTILES; ti++) {
        asm volatile("cp.async.wait_group 2;\n");
        __syncthreads();

        if (ti + 3 < NTILES) {
            int s = (ti + 3) & (NSTAGE - 1);
            const float4* src = reinterpret_cast<const float4*>(
                g_h1 + (size_t)(rbeg + (ti + 3) * PTILE) * H);
            uint32_t d = shbase + s * STAGE_BYTES + j * 16;
            cp16(d, src + j);
            cp16(d + 2048, src + j + 128);
            asm volatile("cp.async.commit_group;\n");
        }

        const float* stage = sh[ti & (NSTAGE - 1)];
        float* outp = g_pre + (size_t)(rbeg + ti * PTILE) * H + j;
#pragma unroll
        for (int i = 0; i < PTILE; i++) {
            const ulonglong2* hp = reinterpret_cast<const ulonglong2*>(stage + i * H);
            u64 a0 = 0, a1 = 0, a2 = 0, a3 = 0;
#pragma unroll
            for (int q = 0; q < 16; q++) {
                ulonglong2 x0 = hp[2 * q], x1 = hp[2 * q + 1];
                a0 = fma2(wp[4 * q + 0], x0.x, a0);
                a1 = fma2(wp[4 * q + 1], x0.y, a1);
                a2 = fma2(wp[4 * q + 2], x1.x, a2);
                a3 = fma2(wp[4 * q + 3], x1.y, a3);
            }
            outp[i * H] = bias + red2(add2(add2(a0, a2), add2(a1, a3)));
        }
        __syncthreads();
    }
}

// ---------------------------------------------------------------------------
extern "C" void kernel_launch(void* const* d_in, const int* in_sizes, int n_in,
                              void* d_out, int out_size) {
    const float* x     = (const float*)d_in[0];
    const float* W_ih0 = (const float*)d_in[1];
    const float* W_hh0 = (const float*)d_in[2];
    const float* b_ih0 = (const float*)d_in[3];
    const float* b_hh0 = (const float*)d_in[4];
    const float* W_ih1 = (const float*)d_in[5];
    const float* W_hh1 = (const float*)d_in[6];
    const float* b_ih1 = (const float*)d_in[7];
    const float* b_hh1 = (const float*)d_in[8];
    float* out = (float*)d_out;

    // Layer 0 input projection -> g_pre
    pre0_kernel<<<BT / P0_ROWS, 128>>>(x, W_ih0, b_ih0, b_hh0);
    // Layer 0 scan (2 rows/CTA): g_pre -> g_h1
    scan_kernel<<<B / 2, 128>>>(0, W_hh0, out);
    // Layer 1 input projection: g_h1 -> g_pre
    proj_kernel<<<PROJ_BLOCKS, 128>>>(W_ih1, b_ih1, b_hh1);
    // Layer 1 scan (2 rows/CTA): g_pre -> out
    scan_kernel<<<B / 2, 128>>>(1, W_hh1, out);
}

// round 9
// speedup vs baseline: 1.0359x; 1.0359x over previous
#include <cuda_runtime.h>
#include <cuda_bf16.h>
#include <cstdint>

#define B   256
#define T   1024
#define H   128
#define I   19
#define BT  (B*T)            // 262144
#define NEL (BT*H)           // 33554432

// Scratch (device global: allocation-free per harness rules)
__device__ float g_pre0[NEL];   // layer-0 pre-activations

typedef unsigned long long u64;

__device__ __forceinline__ u64 fma2(u64 a, u64 b, u64 c) {
    u64 d;
    asm("fma.rn.f32x2 %0, %1, %2, %3;" : "=l"(d) : "l"(a), "l"(b), "l"(c));
    return d;
}
__device__ __forceinline__ u64 add2(u64 a, u64 b) {
    u64 d;
    asm("add.rn.f32x2 %0, %1, %2;" : "=l"(d) : "l"(a), "l"(b));
    return d;
}
__device__ __forceinline__ float red2(u64 a) {
    float x, y;
    asm("mov.b64 {%0, %1}, %2;" : "=f"(x), "=f"(y) : "l"(a));
    return x + y;
}
__device__ __forceinline__ float fast_tanh(float x) {
    float r;
    asm("tanh.approx.f32 %0, %1;" : "=f"(r) : "f"(x));
    return r;
}

// Interleaved 2-row dot: d_r = sum_k W[j,k] * v_r[k], shared W registers.
__device__ __forceinline__ void dot128x2(const u64* __restrict__ wp,
                                         const float* __restrict__ v0,
                                         const float* __restrict__ v1,
                                         float& d0, float& d1) {
    const ulonglong2* h0 = reinterpret_cast<const ulonglong2*>(v0);
    const ulonglong2* h1 = reinterpret_cast<const ulonglong2*>(v1);
    u64 a0=0,a1=0,a2=0,a3=0, c0=0,c1=0,c2=0,c3=0;
#pragma unroll
    for (int i = 0; i < 16; i++) {
        ulonglong2 q0 = h0[2*i], q1 = h0[2*i+1];
        ulonglong2 r0 = h1[2*i], r1 = h1[2*i+1];
        a0 = fma2(wp[4*i+0], q0.x, a0);
        c0 = fma2(wp[4*i+0], r0.x, c0);
        a1 = fma2(wp[4*i+1], q0.y, a1);
        c1 = fma2(wp[4*i+1], r0.y, c1);
        a2 = fma2(wp[4*i+2], q1.x, a2);
        c2 = fma2(wp[4*i+2], r1.x, c2);
        a3 = fma2(wp[4*i+3], q1.y, a3);
        c3 = fma2(wp[4*i+3], r1.y, c3);
    }
    d0 = red2(add2(add2(a0,a2), add2(a1,a3)));
    d1 = red2(add2(add2(c0,c2), add2(c1,c3)));
}

// ---------------------------------------------------------------------------
// Kernel 1: pre0 (proven in round 5)
// ---------------------------------------------------------------------------
#define P0_ROWS 64
#define P0_F4   ((P0_ROWS * I) / 4)   // 304

__global__ void __launch_bounds__(128)
pre0_kernel(const float* __restrict__ x,
            const float* __restrict__ W,
            const float* __restrict__ bi,
            const float* __restrict__ bh) {
    __shared__ __align__(16) float xs[P0_ROWS * I];
    const int j = threadIdx.x;

    float w[I];
#pragma unroll
    for (int f = 0; f < I; f++) w[f] = __ldg(W + j * I + f);
    const float bias = __ldg(bi + j) + __ldg(bh + j);

    const int rbeg = blockIdx.x * P0_ROWS;
    const float4* src = reinterpret_cast<const float4*>(x + (size_t)rbeg * I);
    float4* dst = reinterpret_cast<float4*>(xs);
    dst[j] = src[j];
    dst[j + 128] = src[j + 128];
    if (j < P0_F4 - 256) dst[j + 256] = src[j + 256];
    __syncthreads();

    float* outp = g_pre0 + (size_t)rbeg * H + j;
#pragma unroll 4
    for (int r = 0; r < P0_ROWS; r += 4) {
        float a0 = bias, a1 = bias, a2 = bias, a3 = bias;
#pragma unroll
        for (int f = 0; f < I; f++) {
            a0 = fmaf(xs[(r + 0) * I + f], w[f], a0);
            a1 = fmaf(xs[(r + 1) * I + f], w[f], a1);
            a2 = fmaf(xs[(r + 2) * I + f], w[f], a2);
            a3 = fmaf(xs[(r + 3) * I + f], w[f], a3);
        }
        outp[(r + 0) * H] = a0;
        outp[(r + 1) * H] = a1;
        outp[(r + 2) * H] = a2;
        outp[(r + 3) * H] = a3;
    }
}

// ---------------------------------------------------------------------------
// Kernel 2: FULL two-layer pipeline. 128 CTAs (one wave), 384 threads each,
// 2 batch rows per CTA. Warp-group g = tid>>7:
//   g=0 (A): layer-0 scan      h0(s)   = tanh(pre0(s) + Whh0*h0(s-1))
//   g=1 (B): layer-1 input     p1(s-1) = Wih1*h0(s-1) + b_ih1 + b_hh1
//   g=2 (C): layer-1 scan      h1(s-2) = tanh(p1(s-2) + Whh1*h1(s-3)) -> out
// All vectors live in double-buffered shared; h0 and p1 NEVER touch DRAM.
// One __syncthreads per step; T+2 steps total.
// Buffer parity at step s (par=s&1, q=par^1):
//   A: read h0[q],  write h0[par]
//   B: read h0[q],  write p1[q]
//   C: read p1[par], read h1[q], write h1[par]
// ---------------------------------------------------------------------------
__global__ void __launch_bounds__(384, 1)
rnn_pipeline(const float* __restrict__ Whh0,
             const float* __restrict__ Wih1,
             const float* __restrict__ bi1,
             const float* __restrict__ bh1,
             const float* __restrict__ Whh1,
             float* __restrict__ out) {
    __shared__ __align__(16) float h0buf[2][2][H];
    __shared__ __align__(16) float p1buf[2][2][H];
    __shared__ __align__(16) float h1buf[2][2][H];

    const int tid = threadIdx.x;
    const int g   = tid >> 7;
    const int j   = tid & 127;
    const size_t base0 = (size_t)(2 * blockIdx.x)     * (T * H) + j;
    const size_t base1 = (size_t)(2 * blockIdx.x + 1) * (T * H) + j;

    // Per-group weight row in 64 packed f32x2 registers.
    const float* Wsel = (g == 0) ? Whh0 : (g == 1) ? Wih1 : Whh1;
    u64 wp[64];
    const u64* wrow = reinterpret_cast<const u64*>(Wsel + j * H);
#pragma unroll
    for (int i = 0; i < 64; i++) wp[i] = __ldg(wrow + i);

    const float bias1 = (g == 1) ? (__ldg(bi1 + j) + __ldg(bh1 + j)) : 0.0f;

    // Zero the buffers read at pipeline start.
    if (g == 0) { h0buf[1][0][j] = 0.0f; h0buf[1][1][j] = 0.0f; }
    if (g == 2) { h1buf[1][0][j] = 0.0f; h1buf[1][1][j] = 0.0f; }

    // A's 2-deep pre0 prefetch registers.
    float pc0 = 0.f, pc1 = 0.f, pn0 = 0.f, pn1 = 0.f;
    if (g == 0) {
        pc0 = __ldg(g_pre0 + base0);
        pc1 = __ldg(g_pre0 + base1);
        pn0 = __ldg(g_pre0 + base0 + H);
        pn1 = __ldg(g_pre0 + base1 + H);
    }
    __syncthreads();

#pragma unroll 1
    for (int s = 0; s < T + 2; s++) {
        const int par = s & 1, q = par ^ 1;
        if (g == 0) {
            if (s < T) {
                float d0, d1;
                dot128x2(wp, h0buf[q][0], h0buf[q][1], d0, d1);
                float v0 = fast_tanh(pc0 + d0);
                float v1 = fast_tanh(pc1 + d1);
                h0buf[par][0][j] = v0;
                h0buf[par][1][j] = v1;
                pc0 = pn0; pc1 = pn1;
                int tn = (s + 2 < T) ? (s + 2) : (T - 1);
                pn0 = __ldg(g_pre0 + base0 + (size_t)tn * H);
                pn1 = __ldg(g_pre0 + base1 + (size_t)tn * H);
            }
        } else if (g == 1) {
            if (s >= 1 && s <= T) {
                float d0, d1;
                dot128x2(wp, h0buf[q][0], h0buf[q][1], d0, d1);
                p1buf[q][0][j] = bias1 + d0;
                p1buf[q][1][j] = bias1 + d1;
            }
        } else {
            if (s >= 2) {
                float d0, d1;
                dot128x2(wp, h1buf[q][0], h1buf[q][1], d0, d1);
                float v0 = fast_tanh(p1buf[par][0][j] + d0);
                float v1 = fast_tanh(p1buf[par][1][j] + d1);
                h1buf[par][0][j] = v0;
                h1buf[par][1][j] = v1;
                out[base0 + (size_t)(s - 2) * H] = v0;
                out[base1 + (size_t)(s - 2) * H] = v1;
            }
        }
        __syncthreads();
    }
}

// ---------------------------------------------------------------------------
extern "C" void kernel_launch(void* const* d_in, const int* in_sizes, int n_in,
                              void* d_out, int out_size) {
    const float* x     = (const float*)d_in[0];
    const float* W_ih0 = (const float*)d_in[1];
    const float* W_hh0 = (const float*)d_in[2];
    const float* b_ih0 = (const float*)d_in[3];
    const float* b_hh0 = (const float*)d_in[4];
    const float* W_ih1 = (const float*)d_in[5];
    const float* W_hh1 = (const float*)d_in[6];
    const float* b_ih1 = (const float*)d_in[7];
    const float* b_hh1 = (const float*)d_in[8];
    float* out = (float*)d_out;

    // Layer 0 input projection -> g_pre0
    pre0_kernel<<<BT / P0_ROWS, 128>>>(x, W_ih0, b_ih0, b_hh0);
    // Everything else in one pipelined persistent kernel.
    rnn_pipeline<<<B / 2, 384>>>(W_hh0, W_ih1, b_ih1, b_hh1, W_hh1, out);
}